// round 2
// baseline (speedup 1.0000x reference)
#include <cuda_runtime.h>
#include <math.h>

#define NK   16
#define DLAT 128
#define MM   100
#define NS   136
#define NB   8192
#define MAIN_ROWS 64
#define MAIN_THREADS 256

// ---------- device scratch (no allocation allowed) ----------
__device__ float g_logpi[NS];
__device__ float g_bb[NS];      // |muB|^2 per state
__device__ float g_cb[NS];      // muB . (muA - muB) per state
__device__ float g_u[NS * MM];  // exp(gamma_s * w_mi^2)
__device__ float g_G[NB * NK];  // z @ mu
__device__ float g_z2[NB];      // |z|^2 per row

// ---------- kernel 0: softmax(pi) + mu copy ----------
__global__ void k_prep0(const float* __restrict__ pi, const float* __restrict__ mu,
                        float* out_pi, float* out_mu) {
    __shared__ float red[256];
    int tid = threadIdx.x;
    float v = (tid < NS) ? pi[tid] : -INFINITY;
    red[tid] = v; __syncthreads();
    for (int off = 128; off >= 1; off >>= 1) {
        if (tid < off) red[tid] = fmaxf(red[tid], red[tid + off]);
        __syncthreads();
    }
    float mx = red[0]; __syncthreads();
    float e = (tid < NS) ? expf(v - mx) : 0.0f;
    red[tid] = e; __syncthreads();
    for (int off = 128; off >= 1; off >>= 1) {
        if (tid < off) red[tid] += red[tid + off];
        __syncthreads();
    }
    float ssum = red[0];
    if (tid < NS) {
        float ps = e / ssum;
        if (out_pi) out_pi[tid] = ps;
        g_logpi[tid] = logf(ps + 1e-30f);
    }
    if (out_mu) {
        for (int i = tid; i < DLAT * NK; i += blockDim.x) out_mu[i] = mu[i];
    }
}

// ---------- kernel 1: per-state constants + u table ----------
__global__ void k_prep_s(const float* __restrict__ mu, const int* __restrict__ A,
                         const int* __restrict__ B, const float* __restrict__ w) {
    int s = blockIdx.x;
    int d = threadIdx.x;  // 128 threads = D
    int ia = A[s], ib = B[s];
    float va = mu[d * NK + ia];
    float vb = mu[d * NK + ib];
    float dv = va - vb;
    __shared__ float r0[128], r1[128], r2[128];
    __shared__ float gam_sh;
    r0[d] = vb * vb;
    r1[d] = vb * dv;
    r2[d] = dv * dv;
    __syncthreads();
    for (int off = 64; off >= 1; off >>= 1) {
        if (d < off) {
            r0[d] += r0[d + off];
            r1[d] += r1[d + off];
            r2[d] += r2[d + off];
        }
        __syncthreads();
    }
    if (d == 0) {
        g_bb[s] = r0[0];
        g_cb[s] = r1[0];
        gam_sh = -0.5f * r2[0];
    }
    __syncthreads();
    if (d < MM) {
        float wv = w[d];
        g_u[s * MM + d] = expf(gam_sh * wv * wv);
    }
}

// ---------- kernel 2: G = z @ mu  and z2 ----------
__global__ void k_gemm_small(const float* __restrict__ z, const float* __restrict__ mu) {
    __shared__ float zs[16][128];
    __shared__ float ms[128][NK];
    int tid = threadIdx.x;
    int b0 = blockIdx.x * 16;
    for (int i = tid; i < 16 * 128; i += 256) {
        zs[i >> 7][i & 127] = z[(b0 + (i >> 7)) * DLAT + (i & 127)];
    }
    for (int i = tid; i < 128 * NK; i += 256) {
        ms[i >> 4][i & 15] = mu[i];
    }
    __syncthreads();
    int r = tid >> 4;
    int k = tid & 15;
    float acc = 0.0f, zz = 0.0f;
#pragma unroll 8
    for (int d = 0; d < 128; d++) {
        float zv = zs[r][d];
        acc = fmaf(zv, ms[d][k], acc);
        if (k == 0) zz = fmaf(zv, zv, zz);
    }
    g_G[(b0 + r) * NK + k] = acc;
    if (k == 0) g_z2[b0 + r] = zz;
}

// ---------- kernel 3: main — Horner + logsumexp ----------
__global__ void k_main(const int* __restrict__ A, const int* __restrict__ B,
                       const float* __restrict__ w, float* __restrict__ out_lp) {
    extern __shared__ char smem[];
    float* su   = (float*)smem;                 // NS*MM        = 13600 f
    float* sG   = su + NS * MM;                 // 64*17        = 1088 f
    float* sz2  = sG + MAIN_ROWS * 17;          // 64 f
    float* sac  = sz2 + MAIN_ROWS;              // NS f
    float* scb  = sac + NS;                     // NS f
    int*   sA   = (int*)(scb + NS);             // NS i
    int*   sB   = sA + NS;                      // NS i
    float* psum = (float*)(sB + NS);            // 4*64 f

    int tid = threadIdx.x;
    int b0 = blockIdx.x * MAIN_ROWS;

    for (int i = tid; i < NS * MM; i += MAIN_THREADS) su[i] = g_u[i];
    for (int i = tid; i < MAIN_ROWS * NK; i += MAIN_THREADS) {
        int r = i >> 4, k = i & 15;
        sG[r * 17 + k] = g_G[(b0 + r) * NK + k];
    }
    if (tid < MAIN_ROWS) sz2[tid] = g_z2[b0 + tid];
    if (tid < NS) {
        sac[tid] = g_logpi[tid] - 0.5f * g_bb[tid];
        scb[tid] = g_cb[tid];
        sA[tid]  = A[tid];
        sB[tid]  = B[tid];
    }
    __syncthreads();

    int r = tid & 63;        // fixed row per thread
    int j = tid >> 6;        // quarter index (warp-uniform)
    float w1 = __ldg(&w[1]); // uniform grid spacing
    float acc = 0.0f;

#pragma unroll 2
    for (int i = 0; i < NS / 4; i++) {
        int s = j + 4 * i;   // warp-uniform state
        int ia = sA[s], ib = sB[s];
        float gA = sG[r * 17 + ia];
        float gB = sG[r * 17 + ib];
        float beta  = gA - gB - scb[s];
        float alpha = sac[s] + gB;
        float rr = expf(beta * w1);
        const float4* up = (const float4*)(su + s * MM);
        float f = 0.0f;
#pragma unroll
        for (int g = (MM / 4) - 1; g >= 0; g--) {
            float4 u4 = up[g];
            f = fmaf(rr, f, u4.w);
            f = fmaf(rr, f, u4.z);
            f = fmaf(rr, f, u4.y);
            f = fmaf(rr, f, u4.x);
        }
        acc += expf(alpha) * f;
    }

    psum[j * 64 + r] = acc;
    __syncthreads();
    if (tid < MAIN_ROWS) {
        float tot = psum[tid] + psum[64 + tid] + psum[128 + tid] + psum[192 + tid];
        const float C = -0.5f * (float)DLAT * 1.8378770664093453f;  // -D/2 * ln(2*pi)
        out_lp[b0 + tid] = C - 0.5f * sz2[tid] - logf((float)MM) + logf(tot);
    }
}

// ---------- launcher ----------
extern "C" void kernel_launch(void* const* d_in, const int* in_sizes, int n_in,
                              void* d_out, int out_size) {
    const float* z  = (const float*)d_in[0];
    const float* mu = (const float*)d_in[1];
    const float* pi = (const float*)d_in[2];
    const float* w  = (const float*)d_in[3];
    const int*   A  = (const int*)d_in[4];
    const int*   B  = (const int*)d_in[5];
    float* out = (float*)d_out;

    float* out_pi = nullptr;
    float* out_mu = nullptr;
    float* out_lp = out;
    if (out_size >= NS + DLAT * NK + NB) {
        out_pi = out;
        out_mu = out + NS;
        out_lp = out + NS + DLAT * NK;
    }

    const int SMEM = (NS * MM + MAIN_ROWS * 17 + MAIN_ROWS + NS * 4 + 4 * MAIN_ROWS) * 4;
    cudaFuncSetAttribute(k_main, cudaFuncAttributeMaxDynamicSharedMemorySize, SMEM);

    k_prep0<<<1, 256>>>(pi, mu, out_pi, out_mu);
    k_prep_s<<<NS, 128>>>(mu, A, B, w);
    k_gemm_small<<<NB / 16, 256>>>(z, mu);
    k_main<<<NB / MAIN_ROWS, MAIN_THREADS, SMEM>>>(A, B, w, out_lp);
}

// round 3
// speedup vs baseline: 1.3097x; 1.3097x over previous
#include <cuda_runtime.h>
#include <math.h>

#define NK   16
#define DLAT 128
#define MM   100
#define NS   136
#define NB   8192
#define ROWS 32
#define THREADS 256
#define NGROUP 8           // THREADS / ROWS
#define SPG 17             // NS / NGROUP
#define ZSTRIDE 132        // row stride for z tile (float4-aligned, bank-skewed)

// ---------- device scratch ----------
__device__ float g_logpi[NS];
__device__ float g_bb[NS];      // |muB|^2
__device__ float g_cb[NS];      // muB . (muA - muB)
__device__ float g_u[NS * MM];  // exp(gamma_s * w_m^2)

// ---------- prep: block 0 = softmax(pi)+outputs; blocks 1..NS = per-state ----------
__global__ void k_prep(const float* __restrict__ pi, const float* __restrict__ mu,
                       const int* __restrict__ A, const int* __restrict__ B,
                       const float* __restrict__ w, float* out_pi, float* out_mu) {
    int tid = threadIdx.x;
    if (blockIdx.x == 0) {
        __shared__ float red[256];
        float v = (tid < NS) ? pi[tid] : -INFINITY;
        red[tid] = v; __syncthreads();
        for (int off = 128; off >= 1; off >>= 1) {
            if (tid < off) red[tid] = fmaxf(red[tid], red[tid + off]);
            __syncthreads();
        }
        float mx = red[0]; __syncthreads();
        float e = (tid < NS) ? expf(v - mx) : 0.0f;
        red[tid] = e; __syncthreads();
        for (int off = 128; off >= 1; off >>= 1) {
            if (tid < off) red[tid] += red[tid + off];
            __syncthreads();
        }
        float ssum = red[0];
        if (tid < NS) {
            float ps = e / ssum;
            if (out_pi) out_pi[tid] = ps;
            g_logpi[tid] = logf(ps + 1e-30f);
        }
        if (out_mu) {
            for (int i = tid; i < DLAT * NK; i += blockDim.x) out_mu[i] = mu[i];
        }
    } else {
        int s = blockIdx.x - 1;
        __shared__ float r0[256], r1[256], r2[256];
        __shared__ float gam_sh;
        int ia = A[s], ib = B[s];
        float vb = 0.0f, dv = 0.0f;
        if (tid < DLAT) {
            float va = mu[tid * NK + ia];
            vb = mu[tid * NK + ib];
            dv = va - vb;
        }
        r0[tid] = vb * vb; r1[tid] = vb * dv; r2[tid] = dv * dv;
        __syncthreads();
        for (int off = 128; off >= 1; off >>= 1) {
            if (tid < off) {
                r0[tid] += r0[tid + off];
                r1[tid] += r1[tid + off];
                r2[tid] += r2[tid + off];
            }
            __syncthreads();
        }
        if (tid == 0) {
            g_bb[s] = r0[0];
            g_cb[s] = r1[0];
            gam_sh = -0.5f * r2[0];
        }
        __syncthreads();
        if (tid < MM) {
            float wv = w[tid];
            g_u[s * MM + tid] = expf(gam_sh * wv * wv);
        }
    }
}

// ---------- main: fused small-GEMM + 4-chain Horner + logsumexp ----------
__global__ void __launch_bounds__(THREADS, 2)
k_main(const float* __restrict__ z, const float* __restrict__ mu,
       const int* __restrict__ A, const int* __restrict__ B,
       const float* __restrict__ w, float* __restrict__ out_lp) {
    extern __shared__ float sm[];
    float* su   = sm;                        // NS*MM = 13600
    float* zs   = su + NS * MM;              // ROWS*ZSTRIDE = 4224
    float* ms   = zs + ROWS * ZSTRIDE;       // 128*16 = 2048
    float* sG   = ms + DLAT * NK;            // 32*17 = 544
    float* sz2  = sG + ROWS * 17;            // 32
    float* sac  = sz2 + ROWS;                // 136
    float* scb  = sac + NS;                  // 136
    int*   sA   = (int*)(scb + NS);          // 136
    int*   sB   = sA + NS;                   // 136
    float* psum = (float*)(sB + NS);         // 8*32 = 256

    int tid = threadIdx.x;
    int b0 = blockIdx.x * ROWS;

    // z tile, float4-coalesced from GMEM, bank-skewed rows in SMEM
    const float4* zg = (const float4*)(z + (size_t)b0 * DLAT);
    for (int i = tid; i < ROWS * DLAT / 4; i += THREADS) {
        int rr = i >> 5;          // 32 float4 per row
        int c4 = i & 31;
        float4 v = zg[i];
        float* dst = zs + rr * ZSTRIDE + c4 * 4;
        dst[0] = v.x; dst[1] = v.y; dst[2] = v.z; dst[3] = v.w;
    }
    for (int i = tid; i < DLAT * NK; i += THREADS) ms[i] = mu[i];
    for (int i = tid; i < NS * MM; i += THREADS) su[i] = g_u[i];
    if (tid < NS) {
        sac[tid] = g_logpi[tid] - 0.5f * g_bb[tid];
        scb[tid] = g_cb[tid];
        sA[tid]  = A[tid];
        sB[tid]  = B[tid];
    }
    __syncthreads();

    // fused GEMM: G[r][k] = z[r] . mu[:,k]; 2 rows per thread; z2 alongside
    {
        int k = tid & 15, r0i = tid >> 4;
#pragma unroll
        for (int it = 0; it < 2; it++) {
            int r = r0i + 16 * it;
            const float* zr = zs + r * ZSTRIDE;
            float acc = 0.0f, zz = 0.0f;
#pragma unroll 8
            for (int d4 = 0; d4 < DLAT / 4; d4++) {
                float4 zv = *(const float4*)(zr + d4 * 4);
                int db = d4 * 4;
                acc = fmaf(zv.x, ms[(db + 0) * NK + k], acc);
                acc = fmaf(zv.y, ms[(db + 1) * NK + k], acc);
                acc = fmaf(zv.z, ms[(db + 2) * NK + k], acc);
                acc = fmaf(zv.w, ms[(db + 3) * NK + k], acc);
                if (k == 0) {
                    zz = fmaf(zv.x, zv.x, zz);
                    zz = fmaf(zv.y, zv.y, zz);
                    zz = fmaf(zv.z, zv.z, zz);
                    zz = fmaf(zv.w, zv.w, zz);
                }
            }
            sG[r * 17 + k] = acc;
            if (k == 0) sz2[r] = zz;
        }
    }
    __syncthreads();

    // main loop: each thread owns row r, state group j (warp-uniform states)
    int r = tid & 31;
    int j = tid >> 5;
    float w1 = w[1];
    float acc = 0.0f;
    const float* gr = sG + r * 17;

#pragma unroll 1
    for (int i = 0; i < SPG; i++) {
        int s = j * SPG + i;
        int ia = sA[s], ib = sB[s];
        float gA = gr[ia];
        float gB = gr[ib];
        float beta  = gA - gB - scb[s];
        float alpha = sac[s] + gB;
        float rr  = __expf(beta * w1);
        float rr2 = rr * rr;
        float rr4 = rr2 * rr2;
        const float4* up = (const float4*)(su + s * MM);
        float f0 = 0.0f, f1 = 0.0f, f2 = 0.0f, f3 = 0.0f;
#pragma unroll
        for (int g = MM / 4 - 1; g >= 0; g--) {
            float4 u4 = up[g];
            f0 = fmaf(rr4, f0, u4.x);
            f1 = fmaf(rr4, f1, u4.y);
            f2 = fmaf(rr4, f2, u4.z);
            f3 = fmaf(rr4, f3, u4.w);
        }
        float f = fmaf(rr, f1, f0) + rr2 * fmaf(rr, f3, f2);
        acc = fmaf(__expf(alpha), f, acc);
    }

    psum[j * 32 + r] = acc;
    __syncthreads();
    if (tid < ROWS) {
        float tot = 0.0f;
#pragma unroll
        for (int q = 0; q < NGROUP; q++) tot += psum[q * 32 + tid];
        const float C = -0.5f * (float)DLAT * 1.8378770664093453f;  // -D/2 ln(2pi)
        out_lp[b0 + tid] = C - 0.5f * sz2[tid] - logf((float)MM) + logf(tot);
    }
}

// ---------- launcher ----------
extern "C" void kernel_launch(void* const* d_in, const int* in_sizes, int n_in,
                              void* d_out, int out_size) {
    const float* z  = (const float*)d_in[0];
    const float* mu = (const float*)d_in[1];
    const float* pi = (const float*)d_in[2];
    const float* w  = (const float*)d_in[3];
    const int*   A  = (const int*)d_in[4];
    const int*   B  = (const int*)d_in[5];
    float* out = (float*)d_out;

    float* out_pi = nullptr;
    float* out_mu = nullptr;
    float* out_lp = out;
    if (out_size >= NS + DLAT * NK + NB) {
        out_pi = out;
        out_mu = out + NS;
        out_lp = out + NS + DLAT * NK;
    }

    const int SMEM = (NS * MM + ROWS * ZSTRIDE + DLAT * NK + ROWS * 17 + ROWS
                      + NS + NS + NS + NS + NGROUP * ROWS) * 4;
    cudaFuncSetAttribute(k_main, cudaFuncAttributeMaxDynamicSharedMemorySize, SMEM);

    k_prep<<<1 + NS, 256>>>(pi, mu, A, B, w, out_pi, out_mu);
    k_main<<<NB / ROWS, THREADS, SMEM>>>(z, mu, A, B, w, out_lp);
}